// round 1
// baseline (speedup 1.0000x reference)
#include <cuda_runtime.h>
#include <cstdint>

// NoiseLinear: out[b,o] = sum_i x[b,i]*w[o,i] + bias[o]
//                       + 0.1 * sum_i eps[b,o,i]*w[o,i]*x[b,i]
// eps = jax.random.normal(jax.random.key(seed), (B, OUT, IN), f32)
// reproduced bit-exactly for the partitionable-threefry path (JAX >= 0.5 default):
//   flat = b*OUT*IN + o*IN + i  (< 2^32 here, so counter hi = 0)
//   (o0,o1) = threefry2x32(key=(0, seed), counter=(0, flat))
//   bits = o0 ^ o1
//   f = bitcast(bits>>9 | 0x3f800000) - 1              in [0,1)
//   u = max(lo, f*(1-lo) + lo),  lo = nextafterf(-1,0) = -0.99999994f
//       (1 - lo rounds to exactly 2.0f in f32)
//   eps = sqrt(2) * erfinv(u)   with XLA's Giles single-precision polynomial

#define B_DIM  64
#define IN_DIM 1024
#define OUT_DIM 4096
#define NOISE_F 0.1f

__device__ __forceinline__ void tf2x32(uint32_t ks1, uint32_t ks2, uint32_t c1,
                                       uint32_t& o0, uint32_t& o1) {
    // 32-bit seed => k1 = 0, so ks0 = 0; ks2 = ks1 ^ 0x1BD11BDA (precomputed).
    // counter hi = 0 for all flat indices here.
    uint32_t x0 = 0u;          // c0(=0) + ks0(=0)
    uint32_t x1 = c1 + ks1;
#define TF_R(r) { x0 += x1; x1 = __funnelshift_l(x1, x1, (r)); x1 ^= x0; }
    TF_R(13) TF_R(15) TF_R(26) TF_R(6)
    x0 += ks1;      x1 += ks2 + 1u;
    TF_R(17) TF_R(29) TF_R(16) TF_R(24)
    x0 += ks2;      x1 += 2u;              // + ks0(=0) + 2
    TF_R(13) TF_R(15) TF_R(26) TF_R(6)
    /* x0 += ks0 */ x1 += ks1 + 3u;
    TF_R(17) TF_R(29) TF_R(16) TF_R(24)
    x0 += ks1;      x1 += ks2 + 4u;
    TF_R(13) TF_R(15) TF_R(26) TF_R(6)
    x0 += ks2;      x1 += 5u;              // + ks0(=0) + 5
#undef TF_R
    o0 = x0; o1 = x1;
}

__device__ __forceinline__ float bits_to_normal(uint32_t bits) {
    float f = __uint_as_float((bits >> 9) | 0x3f800000u) - 1.0f;   // [0,1)
    float u = __fadd_rn(__fmul_rn(f, 2.0f), -0.99999994f);
    u = fmaxf(u, -0.99999994f);
    // XLA ErfInv32 (Giles):
    float w = -__logf(__fmaf_rn(u, -u, 1.0f));                     // -log(1-u^2)
    float p;
    if (w < 5.0f) {
        w -= 2.5f;
        p = 2.81022636e-08f;
        p = __fmaf_rn(p, w, 3.43273939e-07f);
        p = __fmaf_rn(p, w, -3.5233877e-06f);
        p = __fmaf_rn(p, w, -4.39150654e-06f);
        p = __fmaf_rn(p, w, 0.00021858087f);
        p = __fmaf_rn(p, w, -0.00125372503f);
        p = __fmaf_rn(p, w, -0.00417768164f);
        p = __fmaf_rn(p, w, 0.246640727f);
        p = __fmaf_rn(p, w, 1.50140941f);
    } else {
        w = __fsqrt_rn(w) - 3.0f;
        p = -0.000200214257f;
        p = __fmaf_rn(p, w, 0.000100950558f);
        p = __fmaf_rn(p, w, 0.00134934322f);
        p = __fmaf_rn(p, w, -0.00367342844f);
        p = __fmaf_rn(p, w, 0.00573950773f);
        p = __fmaf_rn(p, w, -0.0076224613f);
        p = __fmaf_rn(p, w, 0.00943887047f);
        p = __fmaf_rn(p, w, 1.00167406f);
        p = __fmaf_rn(p, w, 2.83297682f);
    }
    return 1.41421356f * (p * u);          // sqrt(2) in f32
}

// One warp per (b-pair, o). b-pair = (bp, bp+32), bp in [0,32). Lanes stride
// the IN=1024 reduction with float4 loads; 8 independent threefry chains per
// loop body for ILP; butterfly reduce at the end.
__global__ void __launch_bounds__(256, 4)
noise_linear_kernel(const float* __restrict__ x, const float* __restrict__ w,
                    const float* __restrict__ bias, const int* __restrict__ seedp,
                    float* __restrict__ out) {
    const uint32_t ks1 = (uint32_t)seedp[0];
    const uint32_t ks2 = ks1 ^ 0x1BD11BDAu;

    const int gw   = blockIdx.x * (blockDim.x >> 5) + (threadIdx.x >> 5);
    const int lane = threadIdx.x & 31;
    const int o  = gw & (OUT_DIM - 1);
    const int bp = gw >> 12;                 // 0..31
    const int b0 = bp, b1 = bp + 32;

    const float4* __restrict__ wrow  = (const float4*)(w + (size_t)o  * IN_DIM);
    const float4* __restrict__ x0row = (const float4*)(x + (size_t)b0 * IN_DIM);
    const float4* __restrict__ x1row = (const float4*)(x + (size_t)b1 * IN_DIM);

    const uint32_t base0 = (uint32_t)b0 * (OUT_DIM * IN_DIM) + (uint32_t)o * IN_DIM;
    const uint32_t base1 = base0 + 32u * (OUT_DIM * IN_DIM);

    float lin0 = 0.f, lin1 = 0.f, n0 = 0.f, n1 = 0.f;

#pragma unroll 1
    for (int ii = 0; ii < IN_DIM / 128; ++ii) {     // 8 iterations
        const int vec = ii * 32 + lane;             // float4 index in the row
        const float4 w4 = __ldg(wrow  + vec);
        const float4 a4 = __ldg(x0row + vec);
        const float4 b4 = __ldg(x1row + vec);
        const uint32_t ibase = (uint32_t)vec * 4u;
#pragma unroll
        for (int j = 0; j < 4; ++j) {
            const float wv = (&w4.x)[j];
            const float av = (&a4.x)[j];
            const float bv = (&b4.x)[j];
            const uint32_t i = ibase + (uint32_t)j;

            const float t0 = __fmul_rn(wv, av);
            const float t1 = __fmul_rn(wv, bv);
            lin0 = __fadd_rn(lin0, t0);
            lin1 = __fadd_rn(lin1, t1);

            uint32_t r0a, r0b, r1a, r1b;
            tf2x32(ks1, ks2, base0 + i, r0a, r0b);
            tf2x32(ks1, ks2, base1 + i, r1a, r1b);
            const float e0 = bits_to_normal(r0a ^ r0b);
            const float e1 = bits_to_normal(r1a ^ r1b);

            n0 = __fmaf_rn(e0, t0, n0);
            n1 = __fmaf_rn(e1, t1, n1);
        }
    }

    // warp butterfly reduce (4 accumulators)
#pragma unroll
    for (int off = 16; off > 0; off >>= 1) {
        lin0 += __shfl_xor_sync(0xFFFFFFFFu, lin0, off);
        lin1 += __shfl_xor_sync(0xFFFFFFFFu, lin1, off);
        n0   += __shfl_xor_sync(0xFFFFFFFFu, n0,   off);
        n1   += __shfl_xor_sync(0xFFFFFFFFu, n1,   off);
    }

    if (lane == 0) {
        const float bz = __ldg(bias + o);
        out[(size_t)b0 * OUT_DIM + o] = lin0 + bz + NOISE_F * n0;
        out[(size_t)b1 * OUT_DIM + o] = lin1 + bz + NOISE_F * n1;
    }
}

extern "C" void kernel_launch(void* const* d_in, const int* in_sizes, int n_in,
                              void* d_out, int out_size) {
    const float* x    = (const float*)d_in[0];
    const float* w    = (const float*)d_in[1];
    const float* bias = (const float*)d_in[2];
    const int*   seed = (const int*)d_in[3];
    float* out = (float*)d_out;

    // 32 b-pairs * 4096 outputs = 131072 warps; 8 warps/block -> 16384 blocks
    noise_linear_kernel<<<16384, 256>>>(x, w, bias, seed, out);
}